// round 2
// baseline (speedup 1.0000x reference)
#include <cuda_runtime.h>
#include <math.h>

#define BS_TOTAL 4096
#define DM 1024
#define NSTATE 16
#define RDT 64
#define PDIM 96
#define SEQ 2048

// scratch (device globals: no allocation allowed)
__device__ float g_xin[BS_TOTAL * DM];     // x @ w_in
__device__ float g_proj[BS_TOTAL * PDIM];  // x_in @ w_x  (dtlow | B | C)
__device__ float g_dt[BS_TOTAL * DM];      // softplus(dtlow @ w_dt + b)*0.099+0.001
__device__ float g_inp[BS_TOTAL * NSTATE]; // B * ((dt*u) @ A)

// ---------------------------------------------------------------------------
// Kernel 1: x_in[4096,1024] = x[4096,1024] @ w_in[1024,1024]  (fp32 tiled)
// ---------------------------------------------------------------------------
__global__ __launch_bounds__(256) void gemm1_kernel(const float* __restrict__ A,
                                                    const float* __restrict__ B) {
    __shared__ float As[16][132];  // [k][m], padded
    __shared__ float Bs[16][132];  // [k][n], padded (row stride 528B, 16B aligned)
    const int tid = threadIdx.x;
    const int bm = blockIdx.y, bn = blockIdx.x;
    const int tx = tid & 15, ty = tid >> 4;
    const int arow = tid >> 2, acol = (tid & 3) * 4;
    const int brow = tid >> 5, bcol = (tid & 31) * 4;
    const float* Ab = A + (size_t)bm * 128 * DM;
    const float* Bb = B + bn * 128;
    float acc[8][8];
#pragma unroll
    for (int i = 0; i < 8; i++)
#pragma unroll
        for (int j = 0; j < 8; j++) acc[i][j] = 0.f;

    for (int kt = 0; kt < DM; kt += 16) {
        float4 a0 = *(const float4*)(Ab + (size_t)arow * DM + kt + acol);
        float4 a1 = *(const float4*)(Ab + (size_t)(arow + 64) * DM + kt + acol);
        float4 b0 = *(const float4*)(Bb + (size_t)(kt + brow) * DM + bcol);
        float4 b1 = *(const float4*)(Bb + (size_t)(kt + brow + 8) * DM + bcol);
        As[acol + 0][arow] = a0.x; As[acol + 1][arow] = a0.y;
        As[acol + 2][arow] = a0.z; As[acol + 3][arow] = a0.w;
        As[acol + 0][arow + 64] = a1.x; As[acol + 1][arow + 64] = a1.y;
        As[acol + 2][arow + 64] = a1.z; As[acol + 3][arow + 64] = a1.w;
        *(float4*)&Bs[brow][bcol] = b0;
        *(float4*)&Bs[brow + 8][bcol] = b1;
        __syncthreads();
#pragma unroll
        for (int kk = 0; kk < 16; kk++) {
            float ra[8], rb[8];
            *(float4*)&ra[0] = *(const float4*)&As[kk][ty * 8];
            *(float4*)&ra[4] = *(const float4*)&As[kk][ty * 8 + 4];
            *(float4*)&rb[0] = *(const float4*)&Bs[kk][tx * 8];
            *(float4*)&rb[4] = *(const float4*)&Bs[kk][tx * 8 + 4];
#pragma unroll
            for (int i = 0; i < 8; i++)
#pragma unroll
                for (int j = 0; j < 8; j++)
                    acc[i][j] = fmaf(ra[i], rb[j], acc[i][j]);
        }
        __syncthreads();
    }
    float* Cb = g_xin + (size_t)(bm * 128 + ty * 8) * DM + bn * 128 + tx * 8;
#pragma unroll
    for (int i = 0; i < 8; i++) {
        *(float4*)(Cb + (size_t)i * DM)     = make_float4(acc[i][0], acc[i][1], acc[i][2], acc[i][3]);
        *(float4*)(Cb + (size_t)i * DM + 4) = make_float4(acc[i][4], acc[i][5], acc[i][6], acc[i][7]);
    }
}

// ---------------------------------------------------------------------------
// Kernel 2: proj[4096,96] = x_in @ w_x[1024,96]
// ---------------------------------------------------------------------------
__global__ __launch_bounds__(256) void proj_kernel(const float* __restrict__ Wx) {
    __shared__ float As2[32][33];  // [k][row], pad for transposed scalar stores
    __shared__ float Bs2[32][96];
    const int tid = threadIdx.x;
    const int m0 = blockIdx.x * 32;
    const int tx = tid & 15, ty = tid >> 4;  // rows ty*2..+1, cols tx*6..+5
    float acc[2][6];
#pragma unroll
    for (int i = 0; i < 2; i++)
#pragma unroll
        for (int j = 0; j < 6; j++) acc[i][j] = 0.f;

    for (int kt = 0; kt < DM; kt += 32) {
        {
            int r = tid >> 3, c4 = (tid & 7) * 4;
            float4 v = *(const float4*)(g_xin + (size_t)(m0 + r) * DM + kt + c4);
            As2[c4 + 0][r] = v.x; As2[c4 + 1][r] = v.y;
            As2[c4 + 2][r] = v.z; As2[c4 + 3][r] = v.w;
        }
        for (int i = tid; i < 768; i += 256) {
            int r = i / 24, c4 = (i % 24) * 4;
            *(float4*)&Bs2[r][c4] = *(const float4*)(Wx + (size_t)(kt + r) * PDIM + c4);
        }
        __syncthreads();
#pragma unroll
        for (int kk = 0; kk < 32; kk++) {
            float ra0 = As2[kk][ty * 2];
            float ra1 = As2[kk][ty * 2 + 1];
#pragma unroll
            for (int j = 0; j < 6; j++) {
                float bv = Bs2[kk][tx * 6 + j];
                acc[0][j] = fmaf(ra0, bv, acc[0][j]);
                acc[1][j] = fmaf(ra1, bv, acc[1][j]);
            }
        }
        __syncthreads();
    }
#pragma unroll
    for (int i = 0; i < 2; i++)
#pragma unroll
        for (int j = 0; j < 6; j++)
            g_proj[(size_t)(m0 + ty * 2 + i) * PDIM + tx * 6 + j] = acc[i][j];
}

// ---------------------------------------------------------------------------
// Kernel 3: dt[4096,1024] = softplus(dtlow @ w_dt + b_dt)*0.099 + 0.001
// ---------------------------------------------------------------------------
__global__ __launch_bounds__(256) void dt_kernel(const float* __restrict__ Wdt,
                                                 const float* __restrict__ bdt) {
    __shared__ float As[64][64];  // dtlow [row][k]
    __shared__ float Bs[64][68];  // w_dt  [k][d]
    const int tid = threadIdx.x;
    const int m0 = blockIdx.y * 64, d0 = blockIdx.x * 64;
    const int tx = tid & 15, ty = tid >> 4;  // rows ty*4..+3, cols tx*4..+3
    float acc[4][4];
#pragma unroll
    for (int i = 0; i < 4; i++)
#pragma unroll
        for (int j = 0; j < 4; j++) acc[i][j] = 0.f;

    for (int i = tid; i < 1024; i += 256) {
        int r = i >> 4, c4 = (i & 15) * 4;
        *(float4*)&As[r][c4] = *(const float4*)(g_proj + (size_t)(m0 + r) * PDIM + c4);
        *(float4*)&Bs[r][c4] = *(const float4*)(Wdt + (size_t)r * DM + d0 + c4);
    }
    __syncthreads();
#pragma unroll 4
    for (int r = 0; r < 64; r++) {
        float ra[4], rb[4];
#pragma unroll
        for (int i = 0; i < 4; i++) ra[i] = As[ty * 4 + i][r];
        *(float4*)&rb[0] = *(const float4*)&Bs[r][tx * 4];
#pragma unroll
        for (int i = 0; i < 4; i++)
#pragma unroll
            for (int j = 0; j < 4; j++)
                acc[i][j] = fmaf(ra[i], rb[j], acc[i][j]);
    }
#pragma unroll
    for (int i = 0; i < 4; i++)
#pragma unroll
        for (int j = 0; j < 4; j++) {
            float z = acc[i][j] + bdt[d0 + tx * 4 + j];
            float sp = (z > 15.f) ? z : log1pf(__expf(z));
            g_dt[(size_t)(m0 + ty * 4 + i) * DM + d0 + tx * 4 + j] = sp * 0.099f + 0.001f;
        }
}

// ---------------------------------------------------------------------------
// Kernel 4: inp[4096,16] = B * ((dt*u) @ (-exp(A_log)))
// ---------------------------------------------------------------------------
__global__ __launch_bounds__(256) void inp_kernel(const float* __restrict__ A_log) {
    __shared__ float Ssh[64][32];  // (dt*u) tile
    __shared__ float Ash[512];     // -exp(A_log) for this k-chunk, linear [d_local*16+n]
    const int tid = threadIdx.x;
    const int m0 = blockIdx.x * 64;
    const int tx = tid & 15, ty = tid >> 4;  // rows ty*4..+3, col n = tx
    float acc[4] = {0.f, 0.f, 0.f, 0.f};

    for (int kt = 0; kt < DM; kt += 32) {
        int r = tid >> 3, c4 = (tid & 7) * 4;  // r 0..31, and +32
#pragma unroll
        for (int h = 0; h < 2; h++) {
            int rr = r + h * 32;
            size_t off = (size_t)(m0 + rr) * DM + kt + c4;
            float4 dv = *(const float4*)(g_dt + off);
            float4 uv = *(const float4*)(g_xin + off);
            *(float4*)&Ssh[rr][c4] =
                make_float4(dv.x * uv.x, dv.y * uv.y, dv.z * uv.z, dv.w * uv.w);
        }
        for (int i = tid; i < 512; i += 256) Ash[i] = -__expf(A_log[kt * NSTATE + i]);
        __syncthreads();
#pragma unroll
        for (int kk = 0; kk < 32; kk++) {
            float bv = Ash[kk * NSTATE + tx];
#pragma unroll
            for (int i = 0; i < 4; i++)
                acc[i] = fmaf(Ssh[ty * 4 + i][kk], bv, acc[i]);
        }
        __syncthreads();
    }
#pragma unroll
    for (int i = 0; i < 4; i++) {
        int m = m0 + ty * 4 + i;
        g_inp[(size_t)m * NSTATE + tx] = acc[i] * g_proj[(size_t)m * PDIM + RDT + tx];
    }
}

// ---------------------------------------------------------------------------
// Kernel 5: scan. 16 lanes per (b,d) pair, lane = state index n.
//   h[s] = exp(dt[s]*A) * h[s-1] + inp[s];  y[s] = sum_n h*C + Dp*u
// ---------------------------------------------------------------------------
__global__ __launch_bounds__(128) void scan_kernel(const float* __restrict__ A_log,
                                                   const float* __restrict__ Dp,
                                                   float* __restrict__ out) {
    const int tid = threadIdx.x;
    const int g = blockIdx.x * 8 + (tid >> 4);  // (b,d) group, 0..2047
    const int n = tid & 15;
    const int b = g >> 10;
    const int d = g & 1023;
    const float A1 = -expf(A_log[d * NSTATE + n]);
    const float Dpd = Dp[d];
    const float* dtp = g_dt + (size_t)b * SEQ * DM + d;
    const float* up  = g_xin + (size_t)b * SEQ * DM + d;
    const float* ip  = g_inp + (size_t)b * SEQ * NSTATE + n;
    const float* cp  = g_proj + (size_t)b * SEQ * PDIM + RDT + NSTATE + n;
    float* op = out + (size_t)b * SEQ * DM + d;

    float h = 0.f;
    float dtv = dtp[0], uv = up[0], iv = ip[0], cv = cp[0];
    for (int s = 0; s < SEQ; s++) {
        float dtn = 0.f, un = 0.f, inn = 0.f, cn = 0.f;
        if (s + 1 < SEQ) {  // prefetch next step (independent of recurrence)
            dtn = dtp[(size_t)(s + 1) * DM];
            un  = up[(size_t)(s + 1) * DM];
            inn = ip[(s + 1) * NSTATE];
            cn  = cp[(s + 1) * PDIM];
        }
        float e = __expf(dtv * A1);
        h = fmaf(e, h, iv);
        float p = h * cv;
        p += __shfl_xor_sync(0xffffffffu, p, 8);
        p += __shfl_xor_sync(0xffffffffu, p, 4);
        p += __shfl_xor_sync(0xffffffffu, p, 2);
        p += __shfl_xor_sync(0xffffffffu, p, 1);
        if (n == 0) op[(size_t)s * DM] = fmaf(Dpd, uv, p);
        dtv = dtn; uv = un; iv = inn; cv = cn;
    }
}

// ---------------------------------------------------------------------------
extern "C" void kernel_launch(void* const* d_in, const int* in_sizes, int n_in,
                              void* d_out, int out_size) {
    const float* x     = (const float*)d_in[0];
    const float* w_in  = (const float*)d_in[1];
    const float* w_x   = (const float*)d_in[2];
    const float* w_dt  = (const float*)d_in[3];
    const float* b_dt  = (const float*)d_in[4];
    const float* A_log = (const float*)d_in[5];
    const float* Dp    = (const float*)d_in[6];
    float* out = (float*)d_out;

    dim3 g1(DM / 128, BS_TOTAL / 128);  // (8, 32)
    gemm1_kernel<<<g1, 256>>>(x, w_in);
    proj_kernel<<<BS_TOTAL / 32, 256>>>(w_x);
    dim3 g3(DM / 64, BS_TOTAL / 64);    // (16, 64)
    dt_kernel<<<g3, 256>>>(w_dt, b_dt);
    inp_kernel<<<BS_TOTAL / 64, 256>>>(A_log);
    scan_kernel<<<256, 128>>>(A_log, Dp, out);
}

// round 4
// speedup vs baseline: 1.0299x; 1.0299x over previous
#include <cuda_runtime.h>
#include <cstdint>
#include <math.h>

#define BS_TOTAL 4096
#define DM 1024
#define NSTATE 16
#define RDT 64
#define PDIM 96
#define SEQ 2048

// scratch (device globals: no allocation allowed)
__device__ __align__(16) float g_xin[BS_TOTAL * DM];      // x @ w_in
__device__ __align__(16) float g_wT[DM * DM];             // w_in^T [e][k], tf32-rounded
__device__ __align__(16) float g_proj[BS_TOTAL * PDIM];   // x_in @ w_x (dtlow|B|C)
__device__ __align__(16) float g_dt[BS_TOTAL * DM];       // softplus(...)*0.099+0.001
__device__ __align__(16) float g_inp[BS_TOTAL * NSTATE];  // B * ((dt*u) @ A)
__device__ __align__(16) float g_negA[DM * NSTATE];       // -exp(A_log)

__device__ __forceinline__ float round_tf32(float x) {
    uint32_t r;
    asm("cvt.rna.tf32.f32 %0, %1;" : "=r"(r) : "f"(x));
    return __uint_as_float(r);
}

__device__ __forceinline__ void mma_tf32(float* c, const uint32_t* a, const uint32_t* b) {
    asm volatile(
        "mma.sync.aligned.m16n8k8.row.col.f32.tf32.tf32.f32 "
        "{%0,%1,%2,%3}, {%4,%5,%6,%7}, {%8,%9}, {%0,%1,%2,%3};"
        : "+f"(c[0]), "+f"(c[1]), "+f"(c[2]), "+f"(c[3])
        : "r"(a[0]), "r"(a[1]), "r"(a[2]), "r"(a[3]), "r"(b[0]), "r"(b[1]));
}

// ===========================================================================
// Prep: transpose w_in -> g_wT (tf32-rounded); negA table
// ===========================================================================
__global__ void transpose_kernel(const float* __restrict__ W) {
    __shared__ float t[32][33];
    const int x0 = blockIdx.x * 32, y0 = blockIdx.y * 32;
    const int tx = threadIdx.x, ty = threadIdx.y;
#pragma unroll
    for (int i = 0; i < 4; i++)
        t[ty + 8 * i][tx] = W[(size_t)(y0 + ty + 8 * i) * DM + x0 + tx];
    __syncthreads();
#pragma unroll
    for (int i = 0; i < 4; i++)
        g_wT[(size_t)(x0 + ty + 8 * i) * DM + y0 + tx] = round_tf32(t[tx][ty + 8 * i]);
}

__global__ void negA_kernel(const float* __restrict__ A_log) {
    int i = blockIdx.x * 256 + threadIdx.x;
    if (i < DM * NSTATE) g_negA[i] = -__expf(A_log[i]);
}

// ===========================================================================
// Kernel 1: x_in[4096,1024] = x @ w_in via mma.sync tf32 (m16n8k8).
// CTA tile 128x128, 8 warps (4 along M x 2 along N -> 32x64 per warp).
// K-chunk 16, double-buffered smem, padded rows (20 floats, conflict-free).
// ===========================================================================
#define KC 16
#define KPAD 20

__global__ __launch_bounds__(256) void gemm1_mma_kernel(const float* __restrict__ x) {
    __shared__ float As[2][128][KPAD];
    __shared__ float Bs[2][128][KPAD];
    const int tid = threadIdx.x;
    const int wid = tid >> 5, lid = tid & 31;
    const int gid = lid >> 2, tig = lid & 3;  // group id (0..7), thread-in-group (0..3)
    const int wm = wid & 3, wn = wid >> 2;    // warp grid 4x2
    const int m0 = blockIdx.y * 128, n0 = blockIdx.x * 128;

    // global load indices: 512 float4 per tile, 2 per thread
    const int r0 = tid >> 2, c0 = (tid & 3) * 4;          // idx = tid
    const int r1 = (tid + 256) >> 2, c1 = c0;             // idx = tid+256

    float acc[2][8][4];
#pragma unroll
    for (int mi = 0; mi < 2; mi++)
#pragma unroll
        for (int ni = 0; ni < 8; ni++)
#pragma unroll
            for (int q = 0; q < 4; q++) acc[mi][ni][q] = 0.f;

    float4 pa0, pa1, pb0, pb1;
    // prologue: load chunk 0
    pa0 = *(const float4*)(x + (size_t)(m0 + r0) * DM + c0);
    pa1 = *(const float4*)(x + (size_t)(m0 + r1) * DM + c1);
    pb0 = *(const float4*)(g_wT + (size_t)(n0 + r0) * DM + c0);
    pb1 = *(const float4*)(g_wT + (size_t)(n0 + r1) * DM + c1);
    {
        float4 v;
        v = pa0; v.x = round_tf32(v.x); v.y = round_tf32(v.y); v.z = round_tf32(v.z); v.w = round_tf32(v.w);
        *(float4*)&As[0][r0][c0] = v;
        v = pa1; v.x = round_tf32(v.x); v.y = round_tf32(v.y); v.z = round_tf32(v.z); v.w = round_tf32(v.w);
        *(float4*)&As[0][r1][c1] = v;
        *(float4*)&Bs[0][r0][c0] = pb0;
        *(float4*)&Bs[0][r1][c1] = pb1;
    }
    __syncthreads();

    const int NK = DM / KC;  // 64
    for (int kt = 0; kt < NK; kt++) {
        const int buf = kt & 1;
        if (kt + 1 < NK) {
            const int kb = (kt + 1) * KC;
            pa0 = *(const float4*)(x + (size_t)(m0 + r0) * DM + kb + c0);
            pa1 = *(const float4*)(x + (size_t)(m0 + r1) * DM + kb + c1);
            pb0 = *(const float4*)(g_wT + (size_t)(n0 + r0) * DM + kb + c0);
            pb1 = *(const float4*)(g_wT + (size_t)(n0 + r1) * DM + kb + c1);
        }
#pragma unroll
        for (int ks = 0; ks < 2; ks++) {
            const int kk = ks * 8;
            uint32_t a[2][4], b[8][2];
#pragma unroll
            for (int mi = 0; mi < 2; mi++) {
                const int m = wm * 32 + mi * 16 + gid;
                a[mi][0] = __float_as_uint(As[buf][m][kk + tig]);
                a[mi][1] = __float_as_uint(As[buf][m + 8][kk + tig]);
                a[mi][2] = __float_as_uint(As[buf][m][kk + tig + 4]);
                a[mi][3] = __float_as_uint(As[buf][m + 8][kk + tig + 4]);
            }
#pragma unroll
            for (int ni = 0; ni < 8; ni++) {
                const int n = wn * 64 + ni * 8 + gid;
                b[ni][0] = __float_as_uint(Bs[buf][n][kk + tig]);
                b[ni][1] = __float_as_uint(Bs[buf][n][kk + tig + 4]);
            }
#pragma unroll
            for (int mi = 0; mi < 2; mi++)
#pragma unroll
                for (int ni = 0; ni < 8; ni++)
                    mma_tf32(acc[mi][ni], a[mi], b[ni]);
        }
        if (kt + 1 < NK) {
            const int nb = buf ^ 1;
            float4 v;
            v = pa0; v.x = round_tf32(v.x); v.y = round_tf32(v.y); v.z = round_tf32(v.z); v.w = round_tf32(v.w);
            *(float4*)&As[nb][r0][c0] = v;
            v = pa1; v.x = round_tf32(v.x); v.y = round_tf32(v.y); v.z = round_tf32(v.z); v.w = round_tf32(v.w);
            *(float4*)&As[nb][r1][c1] = v;
            *(float4*)&Bs[nb][r0][c0] = pb0;
            *(float4*)&Bs[nb][r1][c1] = pb1;
        }
        __syncthreads();
    }

    // epilogue: c[0]=(gid, tig*2), c[1]=+1col, c[2]=(gid+8, tig*2), c[3]=+1col
#pragma unroll
    for (int mi = 0; mi < 2; mi++) {
        const int mrow = m0 + wm * 32 + mi * 16 + gid;
#pragma unroll
        for (int ni = 0; ni < 8; ni++) {
            const int ncol = n0 + wn * 64 + ni * 8 + tig * 2;
            *(float2*)(g_xin + (size_t)mrow * DM + ncol) =
                make_float2(acc[mi][ni][0], acc[mi][ni][1]);
            *(float2*)(g_xin + (size_t)(mrow + 8) * DM + ncol) =
                make_float2(acc[mi][ni][2], acc[mi][ni][3]);
        }
    }
}

// ===========================================================================
// Kernel 2: proj[4096,96] = x_in @ w_x[1024,96]  (FFMA)
// ===========================================================================
__global__ __launch_bounds__(256) void proj_kernel(const float* __restrict__ Wx) {
    __shared__ float As2[32][33];
    __shared__ float Bs2[32][96];
    const int tid = threadIdx.x;
    const int m0 = blockIdx.x * 32;
    const int tx = tid & 15, ty = tid >> 4;
    float acc[2][6];
#pragma unroll
    for (int i = 0; i < 2; i++)
#pragma unroll
        for (int j = 0; j < 6; j++) acc[i][j] = 0.f;

    for (int kt = 0; kt < DM; kt += 32) {
        {
            int r = tid >> 3, c4 = (tid & 7) * 4;
            float4 v = *(const float4*)(g_xin + (size_t)(m0 + r) * DM + kt + c4);
            As2[c4 + 0][r] = v.x; As2[c4 + 1][r] = v.y;
            As2[c4 + 2][r] = v.z; As2[c4 + 3][r] = v.w;
        }
        for (int i = tid; i < 768; i += 256) {
            int r = i / 24, c4 = (i % 24) * 4;
            *(float4*)&Bs2[r][c4] = *(const float4*)(Wx + (size_t)(kt + r) * PDIM + c4);
        }
        __syncthreads();
#pragma unroll
        for (int kk = 0; kk < 32; kk++) {
            float ra0 = As2[kk][ty * 2];
            float ra1 = As2[kk][ty * 2 + 1];
#pragma unroll
            for (int j = 0; j < 6; j++) {
                float bv = Bs2[kk][tx * 6 + j];
                acc[0][j] = fmaf(ra0, bv, acc[0][j]);
                acc[1][j] = fmaf(ra1, bv, acc[1][j]);
            }
        }
        __syncthreads();
    }
#pragma unroll
    for (int i = 0; i < 2; i++)
#pragma unroll
        for (int j = 0; j < 6; j++)
            g_proj[(size_t)(m0 + ty * 2 + i) * PDIM + tx * 6 + j] = acc[i][j];
}

// ===========================================================================
// Kernel 3: dt = softplus(dtlow @ w_dt + b)*0.099 + 0.001
// ===========================================================================
__global__ __launch_bounds__(256) void dt_kernel(const float* __restrict__ Wdt,
                                                 const float* __restrict__ bdt) {
    __shared__ float As[64][64];
    __shared__ float Bs[64][68];
    const int tid = threadIdx.x;
    const int m0 = blockIdx.y * 64, d0 = blockIdx.x * 64;
    const int tx = tid & 15, ty = tid >> 4;
    float acc[4][4];
#pragma unroll
    for (int i = 0; i < 4; i++)
#pragma unroll
        for (int j = 0; j < 4; j++) acc[i][j] = 0.f;

    for (int i = tid; i < 1024; i += 256) {
        int r = i >> 4, c4 = (i & 15) * 4;
        *(float4*)&As[r][c4] = *(const float4*)(g_proj + (size_t)(m0 + r) * PDIM + c4);
        *(float4*)&Bs[r][c4] = *(const float4*)(Wdt + (size_t)r * DM + d0 + c4);
    }
    __syncthreads();
#pragma unroll 4
    for (int r = 0; r < 64; r++) {
        float ra[4], rb[4];
#pragma unroll
        for (int i = 0; i < 4; i++) ra[i] = As[ty * 4 + i][r];
        *(float4*)&rb[0] = *(const float4*)&Bs[r][tx * 4];
#pragma unroll
        for (int i = 0; i < 4; i++)
#pragma unroll
            for (int j = 0; j < 4; j++)
                acc[i][j] = fmaf(ra[i], rb[j], acc[i][j]);
    }
#pragma unroll
    for (int i = 0; i < 4; i++)
#pragma unroll
        for (int j = 0; j < 4; j++) {
            float z = acc[i][j] + bdt[d0 + tx * 4 + j];
            float sp = (z > 15.f) ? z : log1pf(__expf(z));
            g_dt[(size_t)(m0 + ty * 4 + i) * DM + d0 + tx * 4 + j] = sp * 0.099f + 0.001f;
        }
}

// ===========================================================================
// Kernel 4: inp[m,n] = B[m,n] * sum_k dt[m,k]*u[m,k]*negA[k,n]. Warp per row.
// ===========================================================================
__global__ __launch_bounds__(256) void inp_kernel() {
    const int tid = threadIdx.x;
    const int l = tid & 31;
    const int m = blockIdx.x * 8 + (tid >> 5);
    const float* __restrict__ dtr = g_dt + (size_t)m * DM;
    const float* __restrict__ ur = g_xin + (size_t)m * DM;
    float acc[NSTATE];
#pragma unroll
    for (int n = 0; n < NSTATE; n++) acc[n] = 0.f;

#pragma unroll 4
    for (int j = 0; j < 32; j++) {
        const int k = j * 32 + l;
        const float s = dtr[k] * ur[k];
        const float4* ap = (const float4*)(g_negA + k * NSTATE);
        float4 a0 = ap[0], a1 = ap[1], a2 = ap[2], a3 = ap[3];
        acc[0] = fmaf(s, a0.x, acc[0]);  acc[1] = fmaf(s, a0.y, acc[1]);
        acc[2] = fmaf(s, a0.z, acc[2]);  acc[3] = fmaf(s, a0.w, acc[3]);
        acc[4] = fmaf(s, a1.x, acc[4]);  acc[5] = fmaf(s, a1.y, acc[5]);
        acc[6] = fmaf(s, a1.z, acc[6]);  acc[7] = fmaf(s, a1.w, acc[7]);
        acc[8] = fmaf(s, a2.x, acc[8]);  acc[9] = fmaf(s, a2.y, acc[9]);
        acc[10] = fmaf(s, a2.z, acc[10]); acc[11] = fmaf(s, a2.w, acc[11]);
        acc[12] = fmaf(s, a3.x, acc[12]); acc[13] = fmaf(s, a3.y, acc[13]);
        acc[14] = fmaf(s, a3.z, acc[14]); acc[15] = fmaf(s, a3.w, acc[15]);
    }
    float keep = 0.f;
#pragma unroll
    for (int n = 0; n < NSTATE; n++) {
        float v = acc[n];
        v += __shfl_xor_sync(0xffffffffu, v, 16);
        v += __shfl_xor_sync(0xffffffffu, v, 8);
        v += __shfl_xor_sync(0xffffffffu, v, 4);
        v += __shfl_xor_sync(0xffffffffu, v, 2);
        v += __shfl_xor_sync(0xffffffffu, v, 1);
        if (l == n) keep = v;
    }
    if (l < NSTATE)
        g_inp[(size_t)m * NSTATE + l] = keep * g_proj[(size_t)m * PDIM + RDT + l];
}

// ===========================================================================
// Kernel 5: scan, 16 lanes per (b,d); reductions batched over 8 steps.
// ===========================================================================
__global__ __launch_bounds__(128) void scan_kernel(const float* __restrict__ Dp,
                                                   float* __restrict__ out) {
    const int tid = threadIdx.x;
    const int g = blockIdx.x * 8 + (tid >> 4);  // (b,d) group, 0..2047
    const int n = tid & 15;
    const int b = g >> 10;
    const int d = g & 1023;
    const float A1 = g_negA[d * NSTATE + n];
    const float Dpd = Dp[d];
    const float* __restrict__ dtp = g_dt + (size_t)b * SEQ * DM + d;
    const float* __restrict__ up = g_xin + (size_t)b * SEQ * DM + d;
    const float* __restrict__ ip = g_inp + (size_t)b * SEQ * NSTATE + n;
    const float* __restrict__ cp = g_proj + (size_t)b * SEQ * PDIM + RDT + NSTATE + n;
    float* op = out + (size_t)b * SEQ * DM + d;

    float h = 0.f;
    for (int s0 = 0; s0 < SEQ; s0 += 8) {
        float dtv[8], iv[8], cv[8];
#pragma unroll
        for (int j = 0; j < 8; j++) {  // batched independent loads (MLP)
            dtv[j] = dtp[(size_t)(s0 + j) * DM];
            iv[j] = ip[(s0 + j) * NSTATE];
            cv[j] = cp[(s0 + j) * PDIM];
        }
        float p[8];
#pragma unroll
        for (int j = 0; j < 8; j++) {
            float e = __expf(dtv[j] * A1);  // off the h-chain
            h = fmaf(e, h, iv[j]);          // serial chain: 8 x FFMA
            p[j] = h * cv[j];
        }
#pragma unroll
        for (int j = 0; j < 8; j++) {  // 8 independent shfl chains, pipelined
            p[j] += __shfl_xor_sync(0xffffffffu, p[j], 8);
            p[j] += __shfl_xor_sync(0xffffffffu, p[j], 4);
            p[j] += __shfl_xor_sync(0xffffffffu, p[j], 2);
            p[j] += __shfl_xor_sync(0xffffffffu, p[j], 1);
        }
        if (n == 0) {
#pragma unroll
            for (int j = 0; j < 8; j++)
                op[(size_t)(s0 + j) * DM] = fmaf(Dpd, up[(size_t)(s0 + j) * DM], p[j]);
        }
    }
}

// ===========================================================================
extern "C" void kernel_launch(void* const* d_in, const int* in_sizes, int n_in,
                              void* d_out, int out_size) {
    const float* x     = (const float*)d_in[0];
    const float* w_in  = (const float*)d_in[1];
    const float* w_x   = (const float*)d_in[2];
    const float* w_dt  = (const float*)d_in[3];
    const float* b_dt  = (const float*)d_in[4];
    const float* A_log = (const float*)d_in[5];
    const float* Dp    = (const float*)d_in[6];
    float* out = (float*)d_out;

    transpose_kernel<<<dim3(32, 32), dim3(32, 8)>>>(w_in);
    negA_kernel<<<64, 256>>>(A_log);
    gemm1_mma_kernel<<<dim3(DM / 128, BS_TOTAL / 128), 256>>>(x);
    proj_kernel<<<BS_TOTAL / 32, 256>>>(w_x);
    dt_kernel<<<dim3(DM / 64, BS_TOTAL / 64), 256>>>(w_dt, b_dt);
    inp_kernel<<<BS_TOTAL / 8, 256>>>();
    scan_kernel<<<256, 128>>>(Dp, out);
}

// round 5
// speedup vs baseline: 1.7947x; 1.7426x over previous
#include <cuda_runtime.h>
#include <cstdint>
#include <math.h>

#define BS_TOTAL 4096
#define DM 1024
#define NSTATE 16
#define RDT 64
#define PDIM 96
#define SEQ 2048

// scratch (device globals: no allocation allowed)
__device__ __align__(16) float g_xinT[DM * BS_TOTAL];      // x_in transposed [e][m]
__device__ __align__(16) float g_wT[DM * DM];              // w_in^T [e][k], tf32-rounded
__device__ __align__(16) float g_proj[BS_TOTAL * PDIM];    // row-major (dtlow|B|C)
__device__ __align__(16) float g_projP[8 * BS_TOTAL * PDIM];  // k-split partials
__device__ __align__(16) float g_BT[NSTATE * BS_TOTAL];    // B transposed [n][m]
__device__ __align__(16) float g_CT[NSTATE * BS_TOTAL];    // C transposed [n][m]
__device__ __align__(16) float g_dtT[DM * BS_TOTAL];       // dt transposed [d][m]
__device__ __align__(16) float g_inpP[8 * BS_TOTAL * NSTATE];  // G partials
__device__ __align__(16) float g_inpT[NSTATE * BS_TOTAL];  // inp transposed [n][m]
__device__ __align__(16) float g_negA[DM * NSTATE];        // -exp(A_log)

__device__ __forceinline__ float round_tf32(float x) {
    uint32_t r;
    asm("cvt.rna.tf32.f32 %0, %1;" : "=r"(r) : "f"(x));
    return __uint_as_float(r);
}

__device__ __forceinline__ void mma_tf32(float* c, const uint32_t* a, const uint32_t* b) {
    asm volatile(
        "mma.sync.aligned.m16n8k8.row.col.f32.tf32.tf32.f32 "
        "{%0,%1,%2,%3}, {%4,%5,%6,%7}, {%8,%9}, {%0,%1,%2,%3};"
        : "+f"(c[0]), "+f"(c[1]), "+f"(c[2]), "+f"(c[3])
        : "r"(a[0]), "r"(a[1]), "r"(a[2]), "r"(a[3]), "r"(b[0]), "r"(b[1]));
}

// ===========================================================================
// Prep: transpose w_in -> g_wT (tf32-rounded); negA table
// ===========================================================================
__global__ void transpose_kernel(const float* __restrict__ W) {
    __shared__ float t[32][33];
    const int x0 = blockIdx.x * 32, y0 = blockIdx.y * 32;
    const int tx = threadIdx.x, ty = threadIdx.y;
#pragma unroll
    for (int i = 0; i < 4; i++)
        t[ty + 8 * i][tx] = W[(size_t)(y0 + ty + 8 * i) * DM + x0 + tx];
    __syncthreads();
#pragma unroll
    for (int i = 0; i < 4; i++)
        g_wT[(size_t)(x0 + ty + 8 * i) * DM + y0 + tx] = round_tf32(t[tx][ty + 8 * i]);
}

__global__ void negA_kernel(const float* __restrict__ A_log) {
    int i = blockIdx.x * 256 + threadIdx.x;
    if (i < DM * NSTATE) g_negA[i] = -__expf(A_log[i]);
}

// ===========================================================================
// Kernel 1: x_in = x @ w_in via mma.sync tf32, output TRANSPOSED to g_xinT.
// CTA 128x128, 8 warps (4x2 -> 32x64/warp), K-chunk 16, double-buffered.
// ===========================================================================
#define KC 16
#define KPAD 20

__global__ __launch_bounds__(256) void gemm1_mma_kernel(const float* __restrict__ x) {
    __shared__ float As[2][128][KPAD];
    __shared__ float Bs[2][128][KPAD];
    const int tid = threadIdx.x;
    const int wid = tid >> 5, lid = tid & 31;
    const int gid = lid >> 2, tig = lid & 3;
    const int wm = wid & 3, wn = wid >> 2;
    const int m0 = blockIdx.y * 128, n0 = blockIdx.x * 128;

    const int r0 = tid >> 2, c0 = (tid & 3) * 4;
    const int r1 = (tid + 256) >> 2, c1 = c0;

    float acc[2][8][4];
#pragma unroll
    for (int mi = 0; mi < 2; mi++)
#pragma unroll
        for (int ni = 0; ni < 8; ni++)
#pragma unroll
            for (int q = 0; q < 4; q++) acc[mi][ni][q] = 0.f;

    float4 pa0, pa1, pb0, pb1;
    pa0 = *(const float4*)(x + (size_t)(m0 + r0) * DM + c0);
    pa1 = *(const float4*)(x + (size_t)(m0 + r1) * DM + c1);
    pb0 = *(const float4*)(g_wT + (size_t)(n0 + r0) * DM + c0);
    pb1 = *(const float4*)(g_wT + (size_t)(n0 + r1) * DM + c1);
    {
        float4 v;
        v = pa0; v.x = round_tf32(v.x); v.y = round_tf32(v.y); v.z = round_tf32(v.z); v.w = round_tf32(v.w);
        *(float4*)&As[0][r0][c0] = v;
        v = pa1; v.x = round_tf32(v.x); v.y = round_tf32(v.y); v.z = round_tf32(v.z); v.w = round_tf32(v.w);
        *(float4*)&As[0][r1][c1] = v;
        *(float4*)&Bs[0][r0][c0] = pb0;
        *(float4*)&Bs[0][r1][c1] = pb1;
    }
    __syncthreads();

    const int NK = DM / KC;
    for (int kt = 0; kt < NK; kt++) {
        const int buf = kt & 1;
        if (kt + 1 < NK) {
            const int kb = (kt + 1) * KC;
            pa0 = *(const float4*)(x + (size_t)(m0 + r0) * DM + kb + c0);
            pa1 = *(const float4*)(x + (size_t)(m0 + r1) * DM + kb + c1);
            pb0 = *(const float4*)(g_wT + (size_t)(n0 + r0) * DM + kb + c0);
            pb1 = *(const float4*)(g_wT + (size_t)(n0 + r1) * DM + kb + c1);
        }
#pragma unroll
        for (int ks = 0; ks < 2; ks++) {
            const int kk = ks * 8;
            uint32_t a[2][4], b[8][2];
#pragma unroll
            for (int mi = 0; mi < 2; mi++) {
                const int m = wm * 32 + mi * 16 + gid;
                a[mi][0] = __float_as_uint(As[buf][m][kk + tig]);
                a[mi][1] = __float_as_uint(As[buf][m + 8][kk + tig]);
                a[mi][2] = __float_as_uint(As[buf][m][kk + tig + 4]);
                a[mi][3] = __float_as_uint(As[buf][m + 8][kk + tig + 4]);
            }
#pragma unroll
            for (int ni = 0; ni < 8; ni++) {
                const int n = wn * 64 + ni * 8 + gid;
                b[ni][0] = __float_as_uint(Bs[buf][n][kk + tig]);
                b[ni][1] = __float_as_uint(Bs[buf][n][kk + tig + 4]);
            }
#pragma unroll
            for (int mi = 0; mi < 2; mi++)
#pragma unroll
                for (int ni = 0; ni < 8; ni++)
                    mma_tf32(acc[mi][ni], a[mi], b[ni]);
        }
        if (kt + 1 < NK) {
            const int nb = buf ^ 1;
            float4 v;
            v = pa0; v.x = round_tf32(v.x); v.y = round_tf32(v.y); v.z = round_tf32(v.z); v.w = round_tf32(v.w);
            *(float4*)&As[nb][r0][c0] = v;
            v = pa1; v.x = round_tf32(v.x); v.y = round_tf32(v.y); v.z = round_tf32(v.z); v.w = round_tf32(v.w);
            *(float4*)&As[nb][r1][c1] = v;
            *(float4*)&Bs[nb][r0][c0] = pb0;
            *(float4*)&Bs[nb][r1][c1] = pb1;
        }
        __syncthreads();
    }

    // transposed epilogue: stage 32-col chunks in smem (reuse As region), then
    // write g_xinT[e][m] with coalesced 128-float rows.
    float* st = &As[0][0][0];  // 5120 floats >= 32*132
    const int nibase0 = 0;
#pragma unroll
    for (int c = 0; c < 4; c++) {
        if (wn == (c >> 1)) {
            const int nibase = nibase0 + (c & 1) * 4;
#pragma unroll
            for (int mi = 0; mi < 2; mi++)
#pragma unroll
                for (int ni2 = 0; ni2 < 4; ni2++) {
                    const int ni = nibase + ni2;
#pragma unroll
                    for (int q = 0; q < 4; q++) {
                        const int nl = ni2 * 8 + tig * 2 + (q & 1);
                        const int ml = wm * 32 + mi * 16 + gid + ((q >> 1) * 8);
                        st[nl * 132 + ml] = acc[mi][ni][q];
                    }
                }
        }
        __syncthreads();
        {
            const int rl = tid >> 3, mc = (tid & 7) * 16;
            float* dst = g_xinT + (size_t)(n0 + c * 32 + rl) * BS_TOTAL + m0 + mc;
            const float* src = st + rl * 132 + mc;
#pragma unroll
            for (int q = 0; q < 4; q++) *(float4*)(dst + q * 4) = *(const float4*)(src + q * 4);
        }
        __syncthreads();
    }
}

// ===========================================================================
// Kernel 2: proj partials. Thread handles 2 m (float2), 32 p; k-split 8.
// grid (8 mchunk, 3 pchunk, 8 ksplit), block 256.
// ===========================================================================
__global__ __launch_bounds__(256) void proj_kernel(const float* __restrict__ Wx) {
    __shared__ float wxs[128 * 32];
    const int tid = threadIdx.x;
    const int m0 = blockIdx.x * 512, p0 = blockIdx.y * 32, k0 = blockIdx.z * 128;

    for (int i = tid; i < 128 * 32; i += 256)
        wxs[i] = Wx[(size_t)(k0 + (i >> 5)) * PDIM + p0 + (i & 31)];
    __syncthreads();

    const int m = m0 + tid * 2;
    float acc0[32], acc1[32];
#pragma unroll
    for (int p = 0; p < 32; p++) { acc0[p] = 0.f; acc1[p] = 0.f; }

    for (int kk = 0; kk < 128; kk++) {
        float2 xv = *(const float2*)(g_xinT + (size_t)(k0 + kk) * BS_TOTAL + m);
#pragma unroll
        for (int p4 = 0; p4 < 8; p4++) {
            float4 w = *(const float4*)&wxs[kk * 32 + p4 * 4];
            acc0[p4 * 4 + 0] = fmaf(xv.x, w.x, acc0[p4 * 4 + 0]);
            acc0[p4 * 4 + 1] = fmaf(xv.x, w.y, acc0[p4 * 4 + 1]);
            acc0[p4 * 4 + 2] = fmaf(xv.x, w.z, acc0[p4 * 4 + 2]);
            acc0[p4 * 4 + 3] = fmaf(xv.x, w.w, acc0[p4 * 4 + 3]);
            acc1[p4 * 4 + 0] = fmaf(xv.y, w.x, acc1[p4 * 4 + 0]);
            acc1[p4 * 4 + 1] = fmaf(xv.y, w.y, acc1[p4 * 4 + 1]);
            acc1[p4 * 4 + 2] = fmaf(xv.y, w.z, acc1[p4 * 4 + 2]);
            acc1[p4 * 4 + 3] = fmaf(xv.y, w.w, acc1[p4 * 4 + 3]);
        }
    }
    float* o0 = g_projP + ((size_t)blockIdx.z * BS_TOTAL + m) * PDIM + p0;
    float* o1 = o0 + PDIM;
#pragma unroll
    for (int p4 = 0; p4 < 8; p4++) {
        *(float4*)(o0 + p4 * 4) = make_float4(acc0[p4 * 4], acc0[p4 * 4 + 1], acc0[p4 * 4 + 2], acc0[p4 * 4 + 3]);
        *(float4*)(o1 + p4 * 4) = make_float4(acc1[p4 * 4], acc1[p4 * 4 + 1], acc1[p4 * 4 + 2], acc1[p4 * 4 + 3]);
    }
}

// reduce 8 partials -> g_proj row-major; extract B,C transposed
__global__ __launch_bounds__(256) void proj_reduce_kernel() {
    const int idx = blockIdx.x * 256 + threadIdx.x;  // 0 .. 4096*96-1
    const int m = idx / PDIM, p = idx - m * PDIM;
    float v = 0.f;
#pragma unroll
    for (int ks = 0; ks < 8; ks++)
        v += g_projP[(size_t)ks * BS_TOTAL * PDIM + idx];
    g_proj[idx] = v;
    if (p >= RDT) {
        const int n = p - RDT;
        if (n < NSTATE) g_BT[(size_t)n * BS_TOTAL + m] = v;
        else g_CT[(size_t)(n - NSTATE) * BS_TOTAL + m] = v;
    }
}

// ===========================================================================
// Kernel 3: dt = softplus(dtlow @ w_dt + b)*0.099+0.001, output TRANSPOSED.
// ===========================================================================
__global__ __launch_bounds__(256) void dt_kernel(const float* __restrict__ Wdt,
                                                 const float* __restrict__ bdt) {
    __shared__ float As[64][64];
    __shared__ float Bs[64][68];
    const int tid = threadIdx.x;
    const int m0 = blockIdx.y * 64, d0 = blockIdx.x * 64;
    const int tx = tid & 15, ty = tid >> 4;
    float acc[4][4];
#pragma unroll
    for (int i = 0; i < 4; i++)
#pragma unroll
        for (int j = 0; j < 4; j++) acc[i][j] = 0.f;

    for (int i = tid; i < 1024; i += 256) {
        int r = i >> 4, c4 = (i & 15) * 4;
        *(float4*)&As[r][c4] = *(const float4*)(g_proj + (size_t)(m0 + r) * PDIM + c4);
        *(float4*)&Bs[r][c4] = *(const float4*)(Wdt + (size_t)r * DM + d0 + c4);
    }
    __syncthreads();
#pragma unroll 4
    for (int r = 0; r < 64; r++) {
        float ra[4], rb[4];
#pragma unroll
        for (int i = 0; i < 4; i++) ra[i] = As[ty * 4 + i][r];
        *(float4*)&rb[0] = *(const float4*)&Bs[r][tx * 4];
#pragma unroll
        for (int i = 0; i < 4; i++)
#pragma unroll
            for (int j = 0; j < 4; j++)
                acc[i][j] = fmaf(ra[i], rb[j], acc[i][j]);
    }
#pragma unroll
    for (int i = 0; i < 4; i++)
#pragma unroll
        for (int j = 0; j < 4; j++) {
            float z = acc[i][j] + bdt[d0 + tx * 4 + j];
            float sp = (z > 15.f) ? z : log1pf(__expf(z));
            acc[i][j] = sp * 0.099f + 0.001f;
        }
    // staged transpose -> g_dtT[d][m]
    __syncthreads();
    float* stg = &Bs[0][0];  // 64 x 68
#pragma unroll
    for (int j = 0; j < 4; j++)
        *(float4*)&stg[(tx * 4 + j) * 68 + ty * 4] =
            make_float4(acc[0][j], acc[1][j], acc[2][j], acc[3][j]);
    __syncthreads();
    {
        const int dl = tid >> 2, mc = (tid & 3) * 16;
        float* dst = g_dtT + (size_t)(d0 + dl) * BS_TOTAL + m0 + mc;
        const float* src = stg + dl * 68 + mc;
#pragma unroll
        for (int q = 0; q < 4; q++) *(float4*)(dst + q * 4) = *(const float4*)(src + q * 4);
    }
}

// ===========================================================================
// Kernel 4: G partials: G[m][n] = sum_k dtT[k][m]*xinT[k][m]*negA[k][n]
// grid (16 mchunk, 8 ksplit), block 256 (thread per m).
// ===========================================================================
__global__ __launch_bounds__(256) void inp_part_kernel() {
    __shared__ float nAs[128 * NSTATE];
    const int tid = threadIdx.x;
    const int m0 = blockIdx.x * 256, k0 = blockIdx.y * 128;
    for (int i = tid; i < 128 * NSTATE; i += 256) nAs[i] = g_negA[k0 * NSTATE + i];
    __syncthreads();
    const int m = m0 + tid;
    float acc[NSTATE];
#pragma unroll
    for (int n = 0; n < NSTATE; n++) acc[n] = 0.f;
#pragma unroll 2
    for (int kk = 0; kk < 128; kk++) {
        const float s = g_dtT[(size_t)(k0 + kk) * BS_TOTAL + m] *
                        g_xinT[(size_t)(k0 + kk) * BS_TOTAL + m];
#pragma unroll
        for (int n4 = 0; n4 < 4; n4++) {
            float4 a = *(const float4*)&nAs[kk * NSTATE + n4 * 4];
            acc[n4 * 4 + 0] = fmaf(s, a.x, acc[n4 * 4 + 0]);
            acc[n4 * 4 + 1] = fmaf(s, a.y, acc[n4 * 4 + 1]);
            acc[n4 * 4 + 2] = fmaf(s, a.z, acc[n4 * 4 + 2]);
            acc[n4 * 4 + 3] = fmaf(s, a.w, acc[n4 * 4 + 3]);
        }
    }
    float* o = g_inpP + ((size_t)blockIdx.y * BS_TOTAL + m) * NSTATE;
#pragma unroll
    for (int n4 = 0; n4 < 4; n4++)
        *(float4*)(o + n4 * 4) =
            make_float4(acc[n4 * 4], acc[n4 * 4 + 1], acc[n4 * 4 + 2], acc[n4 * 4 + 3]);
}

// reduce + apply B -> g_inpT[n][m]
__global__ __launch_bounds__(256) void inp_reduce_kernel() {
    const int idx = blockIdx.x * 256 + threadIdx.x;  // 0..65535
    const int m = idx >> 4, n = idx & 15;
    float v = 0.f;
#pragma unroll
    for (int ks = 0; ks < 8; ks++)
        v += g_inpP[(size_t)ks * BS_TOTAL * NSTATE + idx];
    g_inpT[(size_t)n * BS_TOTAL + m] = v * g_BT[(size_t)n * BS_TOTAL + m];
}

// ===========================================================================
// Kernel 5: scan. Block = 16 groups (16 consecutive d), group = 16 lanes (n).
// All streams time-contiguous; outputs staged in smem for coalesced stores.
// ===========================================================================
__global__ __launch_bounds__(256) void scan_kernel(const float* __restrict__ Dp,
                                                   float* __restrict__ out) {
    __shared__ float sy[2][8][16];
    const int tid = threadIdx.x;
    const int grp = tid >> 4, n = tid & 15;
    const int d0 = blockIdx.x * 16, b = blockIdx.y;
    const int d = d0 + grp;
    const float A1 = g_negA[d * NSTATE + n];
    const float Dpd = Dp[d];
    const size_t mb = (size_t)b * SEQ;
    const float* __restrict__ dtp = g_dtT + (size_t)d * BS_TOTAL + mb;
    const float* __restrict__ up = g_xinT + (size_t)d * BS_TOTAL + mb;
    const float* __restrict__ ip = g_inpT + (size_t)n * BS_TOTAL + mb;
    const float* __restrict__ cp = g_CT + (size_t)n * BS_TOTAL + mb;
    float* op = out + mb * DM + d0;

    float4 Da, Db, Ua, Ub, Ia, Ib, Ca, Cb;
    Da = *(const float4*)(dtp); Db = *(const float4*)(dtp + 4);
    Ua = *(const float4*)(up);  Ub = *(const float4*)(up + 4);
    Ia = *(const float4*)(ip);  Ib = *(const float4*)(ip + 4);
    Ca = *(const float4*)(cp);  Cb = *(const float4*)(cp + 4);

    float h = 0.f;
    for (int s0 = 0; s0 < SEQ; s0 += 8) {
        float4 nDa, nDb, nUa, nUb, nIa, nIb, nCa, nCb;
        if (s0 + 8 < SEQ) {
            nDa = *(const float4*)(dtp + s0 + 8); nDb = *(const float4*)(dtp + s0 + 12);
            nUa = *(const float4*)(up + s0 + 8);  nUb = *(const float4*)(up + s0 + 12);
            nIa = *(const float4*)(ip + s0 + 8);  nIb = *(const float4*)(ip + s0 + 12);
            nCa = *(const float4*)(cp + s0 + 8);  nCb = *(const float4*)(cp + s0 + 12);
        }
        float e[8], p[8];
        e[0] = __expf(Da.x * A1); e[1] = __expf(Da.y * A1);
        e[2] = __expf(Da.z * A1); e[3] = __expf(Da.w * A1);
        e[4] = __expf(Db.x * A1); e[5] = __expf(Db.y * A1);
        e[6] = __expf(Db.z * A1); e[7] = __expf(Db.w * A1);
        h = fmaf(e[0], h, Ia.x); p[0] = h * Ca.x;
        h = fmaf(e[1], h, Ia.y); p[1] = h * Ca.y;
        h = fmaf(e[2], h, Ia.z); p[2] = h * Ca.z;
        h = fmaf(e[3], h, Ia.w); p[3] = h * Ca.w;
        h = fmaf(e[4], h, Ib.x); p[4] = h * Cb.x;
        h = fmaf(e[5], h, Ib.y); p[5] = h * Cb.y;
        h = fmaf(e[6], h, Ib.z); p[6] = h * Cb.z;
        h = fmaf(e[7], h, Ib.w); p[7] = h * Cb.w;
#pragma unroll
        for (int j = 0; j < 8; j++) {
            p[j] += __shfl_xor_sync(0xffffffffu, p[j], 8);
            p[j] += __shfl_xor_sync(0xffffffffu, p[j], 4);
            p[j] += __shfl_xor_sync(0xffffffffu, p[j], 2);
            p[j] += __shfl_xor_sync(0xffffffffu, p[j], 1);
        }
        const int buf = (s0 >> 3) & 1;
        if (n == 0) {
            sy[buf][0][grp] = fmaf(Dpd, Ua.x, p[0]);
            sy[buf][1][grp] = fmaf(Dpd, Ua.y, p[1]);
            sy[buf][2][grp] = fmaf(Dpd, Ua.z, p[2]);
            sy[buf][3][grp] = fmaf(Dpd, Ua.w, p[3]);
            sy[buf][4][grp] = fmaf(Dpd, Ub.x, p[4]);
            sy[buf][5][grp] = fmaf(Dpd, Ub.y, p[5]);
            sy[buf][6][grp] = fmaf(Dpd, Ub.z, p[6]);
            sy[buf][7][grp] = fmaf(Dpd, Ub.w, p[7]);
        }
        __syncthreads();
        if (tid < 128) {
            const int j = tid >> 4, dd = tid & 15;
            op[(size_t)(s0 + j) * DM + dd] = sy[buf][j][dd];
        }
        Da = nDa; Db = nDb; Ua = nUa; Ub = nUb;
        Ia = nIa; Ib = nIb; Ca = nCa; Cb = nCb;
    }
}

// ===========================================================================
extern "C" void kernel_launch(void* const* d_in, const int* in_sizes, int n_in,
                              void* d_out, int out_size) {
    const float* x     = (const float*)d_in[0];
    const float* w_in  = (const float*)d_in[1];
    const float* w_x   = (const float*)d_in[2];
    const float* w_dt  = (const float*)d_in[3];
    const float* b_dt  = (const float*)d_in[4];
    const float* A_log = (const float*)d_in[5];
    const float* Dp    = (const float*)d_in[6];
    float* out = (float*)d_out;

    transpose_kernel<<<dim3(32, 32), dim3(32, 8)>>>(w_in);
    negA_kernel<<<64, 256>>>(A_log);
    gemm1_mma_kernel<<<dim3(DM / 128, BS_TOTAL / 128), 256>>>(x);
    proj_kernel<<<dim3(8, 3, 8), 256>>>(w_x);
    proj_reduce_kernel<<<(BS_TOTAL * PDIM) / 256, 256>>>();
    dt_kernel<<<dim3(DM / 64, BS_TOTAL / 64), 256>>>(w_dt, b_dt);
    inp_part_kernel<<<dim3(16, 8), 256>>>();
    inp_reduce_kernel<<<(BS_TOTAL * NSTATE) / 256, 256>>>();
    scan_kernel<<<dim3(64, 2), 256>>>(Dp, out);
}